// round 9
// baseline (speedup 1.0000x reference)
#include <cuda_runtime.h>

// inputs [4,320,320,2] f32 -> output [4,320,320,6] f32
#define NB   4
#define NH   320
#define NW   320
#define NIMG 8

// Scratch: per-image squared 1D column distances g2[img][h][w].
__device__ float g2_scratch[NIMG * NH * NW];

// -------------------------------------------------------------------------
// Kernel 1: column pass, segmented for parallelism (unchanged - it won).
// grid (NIMG, NW/32), block (32, 10): 32 columns x 10 row-segments of 32.
// Sentinels (-32768 / 20000) give g^2 >= 4e8: exp underflows to exactly 0
// for all sigmas and can never beat a real candidate -> matches BIG=1e5.
// -------------------------------------------------------------------------
#define CW   32
#define NSEG 10
#define SEGH 32

__global__ void __launch_bounds__(CW * NSEG) col_pass_kernel(const float* __restrict__ in) {
    __shared__ short smLast[NH][CW];      // 20 KB
    __shared__ short segLast[NSEG][CW];
    __shared__ short segFirst[NSEG][CW];
    __shared__ short incLast[NSEG][CW];
    __shared__ short incNxt[NSEG][CW];

    const int img = blockIdx.x;           // 0..7
    const int b   = img >> 1;
    const int c   = img & 1;
    const int wt  = threadIdx.x;          // 0..31
    const int seg = threadIdx.y;          // 0..9
    const int w   = blockIdx.y * CW + wt;
    const int h0  = seg * SEGH;

    const float* __restrict__ base = in + (((size_t)b * NH) * NW + w) * 2 + c;

    float v[SEGH];
    #pragma unroll
    for (int u = 0; u < SEGH; ++u)
        v[u] = base[(size_t)(h0 + u) * (NW * 2)];

    int last = -32768, first = 20000;
    #pragma unroll
    for (int u = 0; u < SEGH; ++u) {
        int h = h0 + u;
        if ((1.0f - v[u]) * 127.5f < 1.0f) {
            last = h;
            if (first == 20000) first = h;
        }
        smLast[h][wt] = (short)last;
    }
    segLast[seg][wt]  = (short)last;
    segFirst[seg][wt] = (short)first;
    __syncthreads();

    if (seg == 0) {
        int acc = -32768;
        #pragma unroll
        for (int s = 0; s < NSEG; ++s) {
            incLast[s][wt] = (short)acc;
            acc = max(acc, (int)segLast[s][wt]);
        }
        int acc2 = 20000;
        #pragma unroll
        for (int s = NSEG - 1; s >= 0; --s) {
            incNxt[s][wt] = (short)acc2;
            acc2 = min(acc2, (int)segFirst[s][wt]);
        }
    }
    __syncthreads();

    float* __restrict__ sc = g2_scratch + (size_t)img * NH * NW + w;
    const int inc = incLast[seg][wt];
    int nxt = incNxt[seg][wt];
    #pragma unroll
    for (int u = SEGH - 1; u >= 0; --u) {
        int h = h0 + u;
        int lastv = max((int)smLast[h][wt], inc);
        if (lastv == h) nxt = h;
        float g = (float)min(h - lastv, nxt - h);
        sc[(size_t)h * NW] = g * g;
    }
}

// -------------------------------------------------------------------------
// Kernel 2: row pass. One thread per pixel j, both channels.
// Speculative 9-tile (36-col, >= +-16) window evaluated branch-free with all
// loads issued up front; exact pruned expansion only beyond the window
// (entered by ~0.2% of threads). grid NB*NH, block 320.
// -------------------------------------------------------------------------
#define NT4  (NW / 4)   // 80 four-wide tiles
#define WTIL 9          // window tiles (covers >= +-16 columns around j)

__global__ void __launch_bounds__(NW) row_pass_kernel(float* __restrict__ out) {
    const int bh = blockIdx.x;            // b*320 + h
    const int j  = threadIdx.x;
    const int b  = bh / NH;
    const int h  = bh - b * NH;

    __shared__ __align__(16) float sh0[NW];
    __shared__ __align__(16) float sh1[NW];

    sh0[j] = g2_scratch[(((size_t)(b * 2 + 0) * NH) + h) * NW + j];
    sh1[j] = g2_scratch[(((size_t)(b * 2 + 1) * NH) + h) * NW + j];
    __syncthreads();

    const float4* __restrict__ v0 = (const float4*)sh0;
    const float4* __restrict__ v1 = (const float4*)sh1;

    const float fj = (float)j;

    // Clamped window of WTIL aligned 4-wide tiles centered on j's tile.
    const int tb0 = j >> 2;
    int ws = tb0 - (WTIL / 2);
    if (ws < 0) ws = 0;
    if (ws > NT4 - WTIL) ws = NT4 - WTIL;

    // Preload all window tiles (high MLP, single latency exposure).
    float4 A[WTIL], C[WTIL];
    #pragma unroll
    for (int s = 0; s < WTIL; ++s) {
        A[s] = v0[ws + s];
        C[s] = v1[ws + s];
    }

    float m0 = 3e38f, m1 = 3e38f;
    const float dbase = fj - (float)(4 * ws);
    #pragma unroll
    for (int s = 0; s < WTIL; ++s) {
        float d0 = dbase - (float)(4 * s);
        float d1 = d0 - 1.0f, d2 = d0 - 2.0f, d3 = d0 - 3.0f;
        float r0 = fmaf(d0, d0, A[s].x), r1 = fmaf(d1, d1, A[s].y);
        float r2 = fmaf(d2, d2, A[s].z), r3 = fmaf(d3, d3, A[s].w);
        m0 = fminf(m0, fminf(fminf(r0, r1), fminf(r2, r3)));
        float s0 = fmaf(d0, d0, C[s].x), s1 = fmaf(d1, d1, C[s].y);
        float s2 = fmaf(d2, d2, C[s].z), s3 = fmaf(d3, d3, C[s].w);
        m1 = fminf(m1, fminf(fminf(s0, s1), fminf(s2, s3)));
    }

    // Exact fallback expansion beyond the window (rare).
    {
        auto evalTile4 = [&](int tb) {
            float4 a = v0[tb];
            float4 c = v1[tb];
            float d0 = fj - (float)(tb * 4);
            float d1 = d0 - 1.0f, d2 = d0 - 2.0f, d3 = d0 - 3.0f;
            float r0 = fmaf(d0, d0, a.x), r1 = fmaf(d1, d1, a.y);
            float r2 = fmaf(d2, d2, a.z), r3 = fmaf(d3, d3, a.w);
            m0 = fminf(m0, fminf(fminf(r0, r1), fminf(r2, r3)));
            float s0 = fmaf(d0, d0, c.x), s1 = fmaf(d1, d1, c.y);
            float s2 = fmaf(d2, d2, c.z), s3 = fmaf(d3, d3, c.w);
            m1 = fminf(m1, fminf(fminf(s0, s1), fminf(s2, s3)));
        };

        int tl = ws - 1;
        int tr = ws + WTIL;
        float dL = fj - (float)(4 * tl + 3);  // min distance into left tile
        float dR = (float)(4 * tr) - fj;      // min distance into right tile

        for (;;) {
            float mM = fmaxf(m0, m1);
            bool needL = (tl >= 0)   && (dL * dL <= mM);
            bool needR = (tr < NT4)  && (dR * dR <= mM);
            if (!(needL || needR)) break;
            if (needL) { evalTile4(tl); --tl; dL += 4.0f; }
            if (needR) { evalTile4(tr); ++tr; dR += 4.0f; }
        }
    }

    // sigmas = [0.02,0.08,0.16]*320 -> 2*sigma^2 = [81.92, 1310.72, 5242.88]
    const float inv0 = 1.0f / 81.92f;
    const float inv1 = 1.0f / 1310.72f;
    const float inv2 = 1.0f / 5242.88f;

    float* __restrict__ o = out + ((size_t)bh * NW + j) * 6;
    float2 p0 = make_float2(__expf(-m0 * inv0), __expf(-m0 * inv1));
    float2 p1 = make_float2(__expf(-m0 * inv2), __expf(-m1 * inv0));
    float2 p2 = make_float2(__expf(-m1 * inv1), __expf(-m1 * inv2));
    ((float2*)o)[0] = p0;
    ((float2*)o)[1] = p1;
    ((float2*)o)[2] = p2;
}

extern "C" void kernel_launch(void* const* d_in, const int* in_sizes, int n_in,
                              void* d_out, int out_size) {
    const float* in = (const float*)d_in[0];
    float* out = (float*)d_out;
    (void)in_sizes; (void)n_in; (void)out_size;

    dim3 g1(NIMG, NW / CW);
    dim3 b1(CW, NSEG);
    col_pass_kernel<<<g1, b1>>>(in);
    row_pass_kernel<<<NB * NH, NW>>>(out);
}